// round 3
// baseline (speedup 1.0000x reference)
#include <cuda_runtime.h>
#include <cuda_bf16.h>
#include <cstdint>

#define N_NODES 50000
#define N_EDGES 600000
#define LATENT 128
#define IN_FEAT 7
#define STEPS 3

// -------- scratch (static device globals; no allocation) --------
__device__ float g_h [N_NODES * LATENT];
__device__ float g_x1[N_NODES * LATENT];
__device__ float g_x2[N_NODES * LATENT];
__device__ float g_deg_s[N_NODES];
__device__ float g_inv_s[N_NODES];
__device__ int   g_cnt_r[N_NODES];
__device__ int   g_off  [N_NODES + 1];
__device__ int   g_cursor[N_NODES];
__device__ int   g_esrc [N_EDGES];
__device__ int   g_incl [50176];
__device__ int   g_bsum [64];
__device__ int   g_boff [64];

__device__ __forceinline__ float* selbuf(int s) {
    return (s == 0) ? g_h : (s == 1) ? g_x1 : g_x2;
}

__device__ __forceinline__ uint32_t f2tf32(float x) {
    uint32_t r;
    asm("cvt.rna.tf32.f32 %0, %1;" : "=r"(r) : "f"(x));
    return r;
}

// ---------------- degree / CSR build ----------------
__global__ void k_zero() {
    int i = blockIdx.x * blockDim.x + threadIdx.x;
    if (i < N_NODES) { g_deg_s[i] = 0.f; g_cnt_r[i] = 0; }
}

__global__ void k_count(const int* __restrict__ snd, const int* __restrict__ rcv) {
    int e = blockIdx.x * blockDim.x + threadIdx.x;
    if (e < N_EDGES) {
        atomicAdd(&g_deg_s[snd[e]], 1.0f);
        atomicAdd(&g_cnt_r[rcv[e]], 1);
    }
}

__global__ void k_scan1() {
    int i = blockIdx.x * 1024 + threadIdx.x;
    int v = (i < N_NODES) ? g_cnt_r[i] : 0;
    int x = v;
    #pragma unroll
    for (int d = 1; d < 32; d <<= 1) {
        int y = __shfl_up_sync(0xFFFFFFFFu, x, d);
        if ((threadIdx.x & 31) >= d) x += y;
    }
    __shared__ int wsum[32];
    if ((threadIdx.x & 31) == 31) wsum[threadIdx.x >> 5] = x;
    __syncthreads();
    if (threadIdx.x < 32) {
        int y = wsum[threadIdx.x];
        #pragma unroll
        for (int d = 1; d < 32; d <<= 1) {
            int z = __shfl_up_sync(0xFFFFFFFFu, y, d);
            if (threadIdx.x >= d) y += z;
        }
        wsum[threadIdx.x] = y;
    }
    __syncthreads();
    if (threadIdx.x >= 32) x += wsum[(threadIdx.x >> 5) - 1];
    g_incl[i] = x;
    if (threadIdx.x == 1023) g_bsum[blockIdx.x] = x;
}

__global__ void k_scan2(int nblocks) {
    if (threadIdx.x == 0 && blockIdx.x == 0) {
        int run = 0;
        for (int i = 0; i < nblocks; i++) { g_boff[i] = run; run += g_bsum[i]; }
    }
}

__global__ void k_scan3() {
    int i = blockIdx.x * 1024 + threadIdx.x;
    if (i < N_NODES) {
        int v = g_cnt_r[i];
        int e = g_boff[blockIdx.x] + g_incl[i] - v;
        g_off[i] = e;
        g_cursor[i] = e;
        g_inv_s[i] = rsqrtf(fmaxf(g_deg_s[i], 1.0f));
    }
    if (i == 0) g_off[N_NODES] = N_EDGES;
}

__global__ void k_fill(const int* __restrict__ snd, const int* __restrict__ rcv) {
    int e = blockIdx.x * blockDim.x + threadIdx.x;
    if (e < N_EDGES) {
        int r = rcv[e];
        int pos = atomicAdd(&g_cursor[r], 1);
        g_esrc[pos] = snd[e];
    }
}

// ---------------- embed ----------------
__global__ void k_embed(const float* __restrict__ nodes,
                        const float* __restrict__ Wemb,
                        const float* __restrict__ bemb) {
    int idx = blockIdx.x * blockDim.x + threadIdx.x;
    if (idx >= N_NODES * LATENT) return;
    int n = idx >> 7;
    int c = idx & 127;
    float acc = bemb[c];
    #pragma unroll
    for (int k = 0; k < IN_FEAT; k++)
        acc = fmaf(nodes[n * IN_FEAT + k], Wemb[k * LATENT + c], acc);
    g_h[idx] = acc;
}

// ---------------- tf32 tensor-core GEMM ----------------
// C[M,128] = act(A[M,128] @ W[128,128] + b) * rowscale
// Block: 128 rows, 8 warps; warp w -> rows [w*16, w*16+16), all 128 cols.
// mma.sync.aligned.m16n8k8 tf32, fp32 accumulate.
__global__ __launch_bounds__(256, 2) void k_gemm_tc(int srcSel, int dstSel,
                                                    const float* __restrict__ W,
                                                    const float* __restrict__ bias,
                                                    int doRelu, int useInvS) {
    const float* __restrict__ A = selbuf(srcSel);
    float* __restrict__ C = selbuf(dstSel);

    __shared__ uint32_t As[128][17];   // [row][k within chunk], tf32 bits, padded
    __shared__ uint32_t Ws[16][129];   // [k within chunk][col], tf32 bits, padded

    const int tid  = threadIdx.x;
    const int warp = tid >> 5;
    const int lane = tid & 31;
    const int g    = lane >> 2;        // groupID 0..7
    const int tig  = lane & 3;         // thread-in-group 0..3
    const int rowBase = blockIdx.x * 128;
    const int r0 = warp * 16;          // warp's row stripe within block

    // A-load mapping: row = tid>>1 (0..127), k = (tid&1)*8 .. +7
    const int larow = tid >> 1;
    const int lak   = (tid & 1) * 8;
    const bool laOK = (rowBase + larow) < N_NODES;
    const float* Aptr = A + (size_t)(rowBase + larow) * 128 + lak;

    // W-load mapping: krow = tid>>4 (0..15), col = (tid&15)*8 .. +7
    const int lwk = tid >> 4;
    const int lwc = (tid & 15) * 8;
    const float* Wptr = W + lwk * 128 + lwc;

    float c[16][4];
    #pragma unroll
    for (int nt = 0; nt < 16; nt++)
        #pragma unroll
        for (int j = 0; j < 4; j++) c[nt][j] = 0.f;

    for (int ch = 0; ch < 8; ch++) {
        // load + convert A chunk (128x16) and W chunk (16x128)
        {
            float4 a0 = laOK ? *(const float4*)(Aptr + ch * 16)
                             : make_float4(0.f, 0.f, 0.f, 0.f);
            float4 a1 = laOK ? *(const float4*)(Aptr + ch * 16 + 4)
                             : make_float4(0.f, 0.f, 0.f, 0.f);
            As[larow][lak + 0] = f2tf32(a0.x);
            As[larow][lak + 1] = f2tf32(a0.y);
            As[larow][lak + 2] = f2tf32(a0.z);
            As[larow][lak + 3] = f2tf32(a0.w);
            As[larow][lak + 4] = f2tf32(a1.x);
            As[larow][lak + 5] = f2tf32(a1.y);
            As[larow][lak + 6] = f2tf32(a1.z);
            As[larow][lak + 7] = f2tf32(a1.w);

            float4 w0 = *(const float4*)(Wptr + ch * 16 * 128);
            float4 w1 = *(const float4*)(Wptr + ch * 16 * 128 + 4);
            Ws[lwk][lwc + 0] = f2tf32(w0.x);
            Ws[lwk][lwc + 1] = f2tf32(w0.y);
            Ws[lwk][lwc + 2] = f2tf32(w0.z);
            Ws[lwk][lwc + 3] = f2tf32(w0.w);
            Ws[lwk][lwc + 4] = f2tf32(w1.x);
            Ws[lwk][lwc + 5] = f2tf32(w1.y);
            Ws[lwk][lwc + 6] = f2tf32(w1.z);
            Ws[lwk][lwc + 7] = f2tf32(w1.w);
        }
        __syncthreads();

        #pragma unroll
        for (int ks = 0; ks < 2; ks++) {
            const int k0 = ks * 8;
            uint32_t a0 = As[r0 + g][k0 + tig];
            uint32_t a1 = As[r0 + g + 8][k0 + tig];
            uint32_t a2 = As[r0 + g][k0 + tig + 4];
            uint32_t a3 = As[r0 + g + 8][k0 + tig + 4];
            #pragma unroll
            for (int nt = 0; nt < 16; nt++) {
                uint32_t b0 = Ws[k0 + tig][nt * 8 + g];
                uint32_t b1 = Ws[k0 + tig + 4][nt * 8 + g];
                asm volatile(
                    "mma.sync.aligned.m16n8k8.row.col.f32.tf32.tf32.f32 "
                    "{%0,%1,%2,%3}, {%4,%5,%6,%7}, {%8,%9}, {%0,%1,%2,%3};"
                    : "+f"(c[nt][0]), "+f"(c[nt][1]), "+f"(c[nt][2]), "+f"(c[nt][3])
                    : "r"(a0), "r"(a1), "r"(a2), "r"(a3), "r"(b0), "r"(b1));
            }
        }
        __syncthreads();
    }

    // epilogue: bias + relu + optional row scale; C layout:
    // c[nt][0,1] -> row r0+g,   cols nt*8 + tig*2, +1
    // c[nt][2,3] -> row r0+g+8, cols nt*8 + tig*2, +1
    const int rowA = rowBase + r0 + g;
    const int rowB = rowA + 8;
    const bool okA = rowA < N_NODES;
    const bool okB = rowB < N_NODES;
    const float rsA = (useInvS && okA) ? g_inv_s[rowA] : 1.0f;
    const float rsB = (useInvS && okB) ? g_inv_s[rowB] : 1.0f;

    #pragma unroll
    for (int nt = 0; nt < 16; nt++) {
        const int col = nt * 8 + tig * 2;
        const float bx = __ldg(&bias[col]);
        const float by = __ldg(&bias[col + 1]);
        float2 vA, vB;
        vA.x = c[nt][0] + bx; vA.y = c[nt][1] + by;
        vB.x = c[nt][2] + bx; vB.y = c[nt][3] + by;
        if (doRelu) {
            vA.x = fmaxf(vA.x, 0.f); vA.y = fmaxf(vA.y, 0.f);
            vB.x = fmaxf(vB.x, 0.f); vB.y = fmaxf(vB.y, 0.f);
        }
        if (useInvS) {
            vA.x *= rsA; vA.y *= rsA;
            vB.x *= rsB; vB.y *= rsB;
        }
        if (okA) *(float2*)&C[(size_t)rowA * 128 + col] = vA;
        if (okB) *(float2*)&C[(size_t)rowB * 128 + col] = vB;
    }
}

// ---------------- fused aggregate + skip + LayerNorm ----------------
__global__ __launch_bounds__(256) void k_agg_ln(const float* __restrict__ ln_scale,
                                                const float* __restrict__ ln_bias) {
    int node = blockIdx.x * 8 + (threadIdx.x >> 5);
    if (node >= N_NODES) return;
    int lane = threadIdx.x & 31;

    float4 acc = make_float4(0.f, 0.f, 0.f, 0.f);
    int b0 = g_off[node], b1 = g_off[node + 1];
    for (int j = b0; j < b1; j++) {
        int s = g_esrc[j];
        float4 v = *(const float4*)&g_x2[s * 128 + lane * 4];
        acc.x += v.x; acc.y += v.y; acc.z += v.z; acc.w += v.w;
    }
    float invr = rsqrtf(fmaxf((float)(b1 - b0), 1.0f));
    float4 hv = *(const float4*)&g_h[node * 128 + lane * 4];
    float4 u;
    u.x = fmaf(acc.x, invr, hv.x);
    u.y = fmaf(acc.y, invr, hv.y);
    u.z = fmaf(acc.z, invr, hv.z);
    u.w = fmaf(acc.w, invr, hv.w);

    float sum = u.x + u.y + u.z + u.w;
    float sq  = u.x * u.x + u.y * u.y + u.z * u.z + u.w * u.w;
    #pragma unroll
    for (int d = 16; d > 0; d >>= 1) {
        sum += __shfl_xor_sync(0xFFFFFFFFu, sum, d);
        sq  += __shfl_xor_sync(0xFFFFFFFFu, sq, d);
    }
    float mean = sum * (1.0f / 128.0f);
    float var = sq * (1.0f / 128.0f) - mean * mean;
    float rstd = rsqrtf(var + 1e-6f);

    float4 sc = *(const float4*)&ln_scale[lane * 4];
    float4 bi = *(const float4*)&ln_bias[lane * 4];
    float4 o;
    o.x = (u.x - mean) * rstd * sc.x + bi.x;
    o.y = (u.y - mean) * rstd * sc.y + bi.y;
    o.z = (u.z - mean) * rstd * sc.z + bi.z;
    o.w = (u.w - mean) * rstd * sc.w + bi.w;
    *(float4*)&g_h[node * 128 + lane * 4] = o;
}

// ---------------- decoder ----------------
__global__ __launch_bounds__(256) void k_decode(const float* __restrict__ Wdec,
                                                const float* __restrict__ bdec,
                                                float* __restrict__ out) {
    int node = blockIdx.x * 8 + (threadIdx.x >> 5);
    if (node >= N_NODES) return;
    int lane = threadIdx.x & 31;

    float4 hv = *(const float4*)&g_h[node * 128 + lane * 4];
    #pragma unroll
    for (int j = 0; j < IN_FEAT; j++) {
        float p = hv.x * __ldg(&Wdec[(lane * 4 + 0) * IN_FEAT + j])
                + hv.y * __ldg(&Wdec[(lane * 4 + 1) * IN_FEAT + j])
                + hv.z * __ldg(&Wdec[(lane * 4 + 2) * IN_FEAT + j])
                + hv.w * __ldg(&Wdec[(lane * 4 + 3) * IN_FEAT + j]);
        #pragma unroll
        for (int d = 16; d > 0; d >>= 1)
            p += __shfl_xor_sync(0xFFFFFFFFu, p, d);
        if (lane == j) out[node * IN_FEAT + j] = p + bdec[j];
    }
}

extern "C" void kernel_launch(void* const* d_in, const int* in_sizes, int n_in,
                              void* d_out, int out_size) {
    const float* nodes    = (const float*)d_in[0];
    const int*   senders  = (const int*)  d_in[1];
    const int*   receivers= (const int*)  d_in[2];
    const float* W_embed  = (const float*)d_in[3];
    const float* b_embed  = (const float*)d_in[4];
    const float* mlp_W    = (const float*)d_in[5];
    const float* mlp_b    = (const float*)d_in[6];
    const float* ln_scale = (const float*)d_in[7];
    const float* ln_bias  = (const float*)d_in[8];
    const float* W_dec    = (const float*)d_in[9];
    const float* b_dec    = (const float*)d_in[10];
    float* out = (float*)d_out;

    const int SCAN_BLOCKS = (N_NODES + 1023) / 1024;

    k_zero <<<(N_NODES + 255) / 256, 256>>>();
    k_count<<<(N_EDGES + 255) / 256, 256>>>(senders, receivers);
    k_scan1<<<SCAN_BLOCKS, 1024>>>();
    k_scan2<<<1, 32>>>(SCAN_BLOCKS);
    k_scan3<<<SCAN_BLOCKS, 1024>>>();
    k_fill <<<(N_EDGES + 255) / 256, 256>>>(senders, receivers);

    k_embed<<<(N_NODES * LATENT + 255) / 256, 256>>>(nodes, W_embed, b_embed);

    const int GEMM_GRID = (N_NODES + 127) / 128;
    for (int step = 0; step < STEPS; step++) {
        const float* W0 = mlp_W + (size_t)(step * 2 + 0) * LATENT * LATENT;
        const float* W1 = mlp_W + (size_t)(step * 2 + 1) * LATENT * LATENT;
        const float* b0 = mlp_b + (size_t)(step * 2 + 0) * LATENT;
        const float* b1 = mlp_b + (size_t)(step * 2 + 1) * LATENT;
        k_gemm_tc<<<GEMM_GRID, 256>>>(0, 1, W0, b0, 1, 0);
        k_gemm_tc<<<GEMM_GRID, 256>>>(1, 2, W1, b1, 1, 1);
        k_agg_ln<<<(N_NODES + 7) / 8, 256>>>(ln_scale + step * LATENT,
                                             ln_bias + step * LATENT);
    }

    k_decode<<<(N_NODES + 7) / 8, 256>>>(W_dec, b_dec, out);
}

// round 4
// speedup vs baseline: 1.4704x; 1.4704x over previous
#include <cuda_runtime.h>
#include <cuda_bf16.h>
#include <cstdint>

#define N_NODES 50000
#define N_EDGES 600000
#define LATENT 128
#define IN_FEAT 7
#define STEPS 3

// -------- scratch (static device globals; no allocation) --------
__device__ float g_h [N_NODES * LATENT];
__device__ float g_x2[N_NODES * LATENT];
__device__ float g_inv_s[N_NODES];
__device__ int   g_cnt_s[N_NODES];
__device__ int   g_cnt_r[N_NODES];
__device__ int   g_off  [N_NODES + 1];
__device__ int   g_cursor[N_NODES];
__device__ int   g_esrc [N_EDGES];

// ---------------- prologue ----------------
__global__ void k_zero() {
    int i = blockIdx.x * blockDim.x + threadIdx.x;
    if (i < N_NODES) { g_cnt_s[i] = 0; g_cnt_r[i] = 0; }
}

__global__ void k_count(const int* __restrict__ snd, const int* __restrict__ rcv) {
    int e = blockIdx.x * blockDim.x + threadIdx.x;
    if (e < N_EDGES) {
        atomicAdd(&g_cnt_s[snd[e]], 1);
        atomicAdd(&g_cnt_r[rcv[e]], 1);
    }
}

// single-block scan over receiver counts; also emits inv_sqrt of sender degree
__global__ __launch_bounds__(1024) void k_scan_all() {
    __shared__ int warp_sums[32];
    const int t = threadIdx.x;
    const int lane = t & 31;
    const int wid = t >> 5;
    int base = 0;

    const int NT = (N_NODES + 1023) / 1024;  // 49
    for (int j = 0; j < NT; j++) {
        int i = j * 1024 + t;
        int v = (i < N_NODES) ? g_cnt_r[i] : 0;
        int x = v;
        #pragma unroll
        for (int d = 1; d < 32; d <<= 1) {
            int y = __shfl_up_sync(0xFFFFFFFFu, x, d);
            if (lane >= d) x += y;
        }
        if (lane == 31) warp_sums[wid] = x;
        __syncthreads();
        if (t < 32) {
            int y = warp_sums[t];
            #pragma unroll
            for (int d = 1; d < 32; d <<= 1) {
                int z = __shfl_up_sync(0xFFFFFFFFu, y, d);
                if (t >= d) y += z;
            }
            warp_sums[t] = y;
        }
        __syncthreads();
        int incl = x + (wid ? warp_sums[wid - 1] : 0);
        int total = warp_sums[31];
        int excl = base + incl - v;
        if (i < N_NODES) {
            g_off[i] = excl;
            g_cursor[i] = excl;
            g_inv_s[i] = rsqrtf(fmaxf((float)g_cnt_s[i], 1.0f));
        }
        base += total;
        __syncthreads();   // protect warp_sums reuse
    }
    if (t == 0) g_off[N_NODES] = N_EDGES;
}

__global__ void k_fill(const int* __restrict__ snd, const int* __restrict__ rcv) {
    int e = blockIdx.x * blockDim.x + threadIdx.x;
    if (e < N_EDGES) {
        int r = rcv[e];
        int pos = atomicAdd(&g_cursor[r], 1);
        g_esrc[pos] = snd[e];
    }
}

// ---------------- embed ----------------
__global__ void k_embed(const float* __restrict__ nodes,
                        const float* __restrict__ Wemb,
                        const float* __restrict__ bemb) {
    int idx = blockIdx.x * blockDim.x + threadIdx.x;
    if (idx >= N_NODES * LATENT) return;
    int n = idx >> 7;
    int c = idx & 127;
    float acc = bemb[c];
    #pragma unroll
    for (int k = 0; k < IN_FEAT; k++)
        acc = fmaf(nodes[n * IN_FEAT + k], Wemb[k * LATENT + c], acc);
    g_h[idx] = acc;
}

// ---------------- fused dual GEMM ----------------
// x2 = relu( relu(h @ W0 + b0) @ W1 + b1 )   for a 64-row stripe.
// x1 tile (64x128) lives entirely in shared memory.
// Per-stage structure = proven R1 GEMM: BK=16, TM=8 x TN=4, 256 threads.
__global__ __launch_bounds__(256) void k_gemm2(const float* __restrict__ W0,
                                               const float* __restrict__ b0,
                                               const float* __restrict__ W1,
                                               const float* __restrict__ b1) {
    const float* __restrict__ A = g_h;
    float* __restrict__ C = g_x2;

    __shared__ float Ast[16][65];     // stage-1 A chunk, transposed [k][row]
    __shared__ float Ws[16][128];     // weight chunk [k][col]
    __shared__ float X1[64 * 128];    // intermediate tile [row][col]

    const int tid = threadIdx.x;
    const int tx = tid & 31;          // col group (cols tx*4 .. +3)
    const int ty = tid >> 5;          // row group (rows ty*8 .. +7)
    const int rowBase = blockIdx.x * 64;

    // stagers
    const int ar = tid >> 2;          // 0..63
    const int kq = (tid & 3) * 4;     // 0,4,8,12
    const int wr = tid >> 5;          // 0..7
    const int wc = (tid & 31) * 4;    // 0..124

    float acc[8][4];
    #pragma unroll
    for (int i = 0; i < 8; i++)
        #pragma unroll
        for (int j = 0; j < 4; j++) acc[i][j] = 0.f;

    // ---------- stage 1: x1 = relu(A @ W0 + b0) ----------
    const bool arOK = (rowBase + ar) < N_NODES;
    for (int k0 = 0; k0 < 128; k0 += 16) {
        {
            float4 v = arOK ? *(const float4*)&A[(size_t)(rowBase + ar) * 128 + k0 + kq]
                            : make_float4(0.f, 0.f, 0.f, 0.f);
            Ast[kq + 0][ar] = v.x;
            Ast[kq + 1][ar] = v.y;
            Ast[kq + 2][ar] = v.z;
            Ast[kq + 3][ar] = v.w;
            *(float4*)&Ws[wr][wc]     = *(const float4*)&W0[(k0 + wr) * 128 + wc];
            *(float4*)&Ws[wr + 8][wc] = *(const float4*)&W0[(k0 + wr + 8) * 128 + wc];
        }
        __syncthreads();
        #pragma unroll
        for (int k = 0; k < 16; k++) {
            float4 wv = *(const float4*)&Ws[k][tx * 4];
            float a[8];
            #pragma unroll
            for (int i = 0; i < 8; i++) a[i] = Ast[k][ty * 8 + i];
            #pragma unroll
            for (int i = 0; i < 8; i++) {
                acc[i][0] = fmaf(a[i], wv.x, acc[i][0]);
                acc[i][1] = fmaf(a[i], wv.y, acc[i][1]);
                acc[i][2] = fmaf(a[i], wv.z, acc[i][2]);
                acc[i][3] = fmaf(a[i], wv.w, acc[i][3]);
            }
        }
        __syncthreads();
    }
    {
        float4 bv = *(const float4*)&b0[tx * 4];
        #pragma unroll
        for (int i = 0; i < 8; i++) {
            float4 o;
            o.x = fmaxf(acc[i][0] + bv.x, 0.f);
            o.y = fmaxf(acc[i][1] + bv.y, 0.f);
            o.z = fmaxf(acc[i][2] + bv.z, 0.f);
            o.w = fmaxf(acc[i][3] + bv.w, 0.f);
            *(float4*)&X1[(ty * 8 + i) * 128 + tx * 4] = o;
        }
    }
    __syncthreads();

    // ---------- stage 2: x2 = relu(X1 @ W1 + b1) ----------
    #pragma unroll
    for (int i = 0; i < 8; i++)
        #pragma unroll
        for (int j = 0; j < 4; j++) acc[i][j] = 0.f;

    for (int k0 = 0; k0 < 128; k0 += 16) {
        *(float4*)&Ws[wr][wc]     = *(const float4*)&W1[(k0 + wr) * 128 + wc];
        *(float4*)&Ws[wr + 8][wc] = *(const float4*)&W1[(k0 + wr + 8) * 128 + wc];
        __syncthreads();
        #pragma unroll
        for (int k = 0; k < 16; k++) {
            float4 wv = *(const float4*)&Ws[k][tx * 4];
            float a[8];
            #pragma unroll
            for (int i = 0; i < 8; i++) a[i] = X1[(ty * 8 + i) * 128 + k0 + k];  // broadcast
            #pragma unroll
            for (int i = 0; i < 8; i++) {
                acc[i][0] = fmaf(a[i], wv.x, acc[i][0]);
                acc[i][1] = fmaf(a[i], wv.y, acc[i][1]);
                acc[i][2] = fmaf(a[i], wv.z, acc[i][2]);
                acc[i][3] = fmaf(a[i], wv.w, acc[i][3]);
            }
        }
        __syncthreads();
    }
    {
        float4 bv = *(const float4*)&b1[tx * 4];
        #pragma unroll
        for (int i = 0; i < 8; i++) {
            int row = rowBase + ty * 8 + i;
            if (row >= N_NODES) break;
            float4 o;
            o.x = fmaxf(acc[i][0] + bv.x, 0.f);
            o.y = fmaxf(acc[i][1] + bv.y, 0.f);
            o.z = fmaxf(acc[i][2] + bv.z, 0.f);
            o.w = fmaxf(acc[i][3] + bv.w, 0.f);
            *(float4*)&C[(size_t)row * 128 + tx * 4] = o;
        }
    }
}

// ---------------- fused aggregate (with sender scale) + skip + LayerNorm ----------------
__global__ __launch_bounds__(256) void k_agg_ln(const float* __restrict__ ln_scale,
                                                const float* __restrict__ ln_bias) {
    int node = blockIdx.x * 8 + (threadIdx.x >> 5);
    if (node >= N_NODES) return;
    int lane = threadIdx.x & 31;

    float4 acc = make_float4(0.f, 0.f, 0.f, 0.f);
    int b0 = g_off[node], b1 = g_off[node + 1];
    for (int j = b0; j < b1; j++) {
        int s = g_esrc[j];
        float is = g_inv_s[s];
        float4 v = *(const float4*)&g_x2[(size_t)s * 128 + lane * 4];
        acc.x = fmaf(v.x, is, acc.x);
        acc.y = fmaf(v.y, is, acc.y);
        acc.z = fmaf(v.z, is, acc.z);
        acc.w = fmaf(v.w, is, acc.w);
    }
    float invr = rsqrtf(fmaxf((float)(b1 - b0), 1.0f));
    float4 hv = *(const float4*)&g_h[(size_t)node * 128 + lane * 4];
    float4 u;
    u.x = fmaf(acc.x, invr, hv.x);
    u.y = fmaf(acc.y, invr, hv.y);
    u.z = fmaf(acc.z, invr, hv.z);
    u.w = fmaf(acc.w, invr, hv.w);

    float sum = u.x + u.y + u.z + u.w;
    float sq  = u.x * u.x + u.y * u.y + u.z * u.z + u.w * u.w;
    #pragma unroll
    for (int d = 16; d > 0; d >>= 1) {
        sum += __shfl_xor_sync(0xFFFFFFFFu, sum, d);
        sq  += __shfl_xor_sync(0xFFFFFFFFu, sq, d);
    }
    float mean = sum * (1.0f / 128.0f);
    float var = sq * (1.0f / 128.0f) - mean * mean;
    float rstd = rsqrtf(var + 1e-6f);

    float4 sc = *(const float4*)&ln_scale[lane * 4];
    float4 bi = *(const float4*)&ln_bias[lane * 4];
    float4 o;
    o.x = (u.x - mean) * rstd * sc.x + bi.x;
    o.y = (u.y - mean) * rstd * sc.y + bi.y;
    o.z = (u.z - mean) * rstd * sc.z + bi.z;
    o.w = (u.w - mean) * rstd * sc.w + bi.w;
    *(float4*)&g_h[(size_t)node * 128 + lane * 4] = o;
}

// ---------------- decoder ----------------
__global__ __launch_bounds__(256) void k_decode(const float* __restrict__ Wdec,
                                                const float* __restrict__ bdec,
                                                float* __restrict__ out) {
    int node = blockIdx.x * 8 + (threadIdx.x >> 5);
    if (node >= N_NODES) return;
    int lane = threadIdx.x & 31;

    float4 hv = *(const float4*)&g_h[(size_t)node * 128 + lane * 4];
    #pragma unroll
    for (int j = 0; j < IN_FEAT; j++) {
        float p = hv.x * __ldg(&Wdec[(lane * 4 + 0) * IN_FEAT + j])
                + hv.y * __ldg(&Wdec[(lane * 4 + 1) * IN_FEAT + j])
                + hv.z * __ldg(&Wdec[(lane * 4 + 2) * IN_FEAT + j])
                + hv.w * __ldg(&Wdec[(lane * 4 + 3) * IN_FEAT + j]);
        #pragma unroll
        for (int d = 16; d > 0; d >>= 1)
            p += __shfl_xor_sync(0xFFFFFFFFu, p, d);
        if (lane == j) out[node * IN_FEAT + j] = p + bdec[j];
    }
}

extern "C" void kernel_launch(void* const* d_in, const int* in_sizes, int n_in,
                              void* d_out, int out_size) {
    const float* nodes    = (const float*)d_in[0];
    const int*   senders  = (const int*)  d_in[1];
    const int*   receivers= (const int*)  d_in[2];
    const float* W_embed  = (const float*)d_in[3];
    const float* b_embed  = (const float*)d_in[4];
    const float* mlp_W    = (const float*)d_in[5];
    const float* mlp_b    = (const float*)d_in[6];
    const float* ln_scale = (const float*)d_in[7];
    const float* ln_bias  = (const float*)d_in[8];
    const float* W_dec    = (const float*)d_in[9];
    const float* b_dec    = (const float*)d_in[10];
    float* out = (float*)d_out;

    const int GEMM_GRID = (N_NODES + 63) / 64;

    // launch index 3 = k_gemm2 (step 0) -> this is what ncu captures
    k_zero <<<(N_NODES + 255) / 256, 256>>>();                                   // 0
    k_count<<<(N_EDGES + 255) / 256, 256>>>(senders, receivers);                 // 1
    k_embed<<<(N_NODES * LATENT + 255) / 256, 256>>>(nodes, W_embed, b_embed);   // 2
    k_gemm2<<<GEMM_GRID, 256>>>(mlp_W, mlp_b,                                    // 3
                                mlp_W + (size_t)LATENT * LATENT, mlp_b + LATENT);
    k_scan_all<<<1, 1024>>>();                                                   // 4
    k_fill <<<(N_EDGES + 255) / 256, 256>>>(senders, receivers);                 // 5

    for (int step = 0; step < STEPS; step++) {
        if (step > 0) {
            const float* W0 = mlp_W + (size_t)(step * 2 + 0) * LATENT * LATENT;
            const float* W1 = mlp_W + (size_t)(step * 2 + 1) * LATENT * LATENT;
            const float* b0 = mlp_b + (size_t)(step * 2 + 0) * LATENT;
            const float* b1 = mlp_b + (size_t)(step * 2 + 1) * LATENT;
            k_gemm2<<<GEMM_GRID, 256>>>(W0, b0, W1, b1);
        }
        k_agg_ln<<<(N_NODES + 7) / 8, 256>>>(ln_scale + step * LATENT,
                                             ln_bias + step * LATENT);
    }

    k_decode<<<(N_NODES + 7) / 8, 256>>>(W_dec, b_dec, out);
}